// round 2
// baseline (speedup 1.0000x reference)
#include <cuda_runtime.h>

#define B_ 8
#define C_ 128
#define H_ 128
#define W_ 224
#define S_ 81
#define HW_ (H_*W_)

// ---------------- scratch (no allocations allowed) ----------------
__device__ float g_corr[B_*S_*HW_];      // 74.3 MB
__device__ float g_h1  [B_*64*HW_];      // 58.7 MB
__device__ float g_h2  [B_*64*HW_];      // 58.7 MB
__device__ float g_h3  [B_*32*HW_];      // 29.3 MB
__device__ float g_w1r [212*9*64];       // weights reordered [ci][k][oc], ci padded to 212
__device__ float g_w2r [64*9*64];
__device__ float g_w3r [64*9*32];

// ---------------- f32x2 packed-FMA helpers (sm_10x) ----------------
__device__ __forceinline__ unsigned long long pk2(float a, float b) {
    unsigned long long r;
    asm("mov.b64 %0, {%1, %2};" : "=l"(r) : "f"(a), "f"(b));
    return r;
}
__device__ __forceinline__ void upk2(unsigned long long r, float& a, float& b) {
    asm("mov.b64 {%0, %1}, %2;" : "=f"(a), "=f"(b) : "l"(r));
}
__device__ __forceinline__ void fma2(unsigned long long& d, unsigned long long a, unsigned long long b) {
    asm("fma.rn.f32x2 %0, %1, %2, %0;" : "+l"(d) : "l"(a), "l"(b));
}

// ---------------- weight reorder: [oc][ci][k] -> [ci][k][oc], zero-pad ci ----------------
__global__ void k_reorder(const float* __restrict__ w, float* __restrict__ wr,
                          int CIN, int CINP, int COUT) {
    int i = blockIdx.x * 256 + threadIdx.x;
    int total = CINP * 9 * COUT;
    if (i >= total) return;
    int oc = i % COUT;
    int t  = i / COUT;
    int k  = t % 9;
    int ci = t / 9;
    wr[i] = (ci < CIN) ? w[(oc * CIN + ci) * 9 + k] : 0.0f;
}

// ---------------- correlation: 81 shifts, mean over 128 channels ----------------
// tile: 32 cols x 8 rows, 1 px/thread, 81 register accumulators.
__global__ void __launch_bounds__(256) k_corr(const float* __restrict__ x1,
                                              const float* __restrict__ x2) {
    __shared__ __align__(16) float x2s[4][16][40];
    const int tid = threadIdx.x;
    const int col = tid & 31, row = tid >> 5;
    const int w0 = blockIdx.x * 32, h0 = blockIdx.y * 8, b = blockIdx.z;

    float acc[81];
#pragma unroll
    for (int s = 0; s < 81; s++) acc[s] = 0.f;

    for (int c0 = 0; c0 < C_; c0 += 4) {
        __syncthreads();
        // x2 halo: rows h0-4..h0+11, cols w0-4..w0+35
        for (int idx = tid; idx < 4 * 16 * 40; idx += 256) {
            int c = idx / 640, r2 = idx % 640, rr = r2 / 40, cc = r2 % 40;
            int gh = h0 + rr - 4, gw = w0 + cc - 4;
            float v = 0.f;
            if (gh >= 0 && gh < H_ && gw >= 0 && gw < W_)
                v = x2[((b * C_ + c0 + c) * H_ + gh) * W_ + gw];
            x2s[c][rr][cc] = v;
        }
        float x1r[4];
#pragma unroll
        for (int c = 0; c < 4; c++)
            x1r[c] = x1[((b * C_ + c0 + c) * H_ + h0 + row) * W_ + w0 + col];
        __syncthreads();
#pragma unroll
        for (int c = 0; c < 4; c++) {
            float v = x1r[c];
#pragma unroll
            for (int dy = 0; dy < 9; dy++)
#pragma unroll
                for (int dx = 0; dx < 9; dx++)
                    acc[dy * 9 + dx] += v * x2s[c][row + dy][col + dx];
        }
    }
#pragma unroll
    for (int s = 0; s < 81; s++)
        g_corr[((b * S_ + s) * H_ + h0 + row) * W_ + w0 + col] = acc[s] * (1.0f / 128.0f);
}

// ---------------- direct 3x3 conv, f32x2 accumulators ----------------
// 256 thr = 32 px-threads x 8 oc-threads. Output tile: 8 rows x 32 cols x COUT oc.
// Each thread: 8 rows x OCPT ocs (packed as OCPT/2 f32x2 accumulators).
// SPLIT: input channels 0..127 from `in` (x1), 128..208 from `in2` (corr).
template<int CIN, int CINP, int COUT, int OCPT, bool LEAKY, bool SPLIT>
__global__ void __launch_bounds__(256) k_conv(const float* __restrict__ in,
                                              const float* __restrict__ in2,
                                              const float* __restrict__ wr,
                                              const float* __restrict__ bias,
                                              float* __restrict__ out) {
    __shared__ __align__(16) float in_s[4][10][34];
    __shared__ __align__(16) float w_s[4 * 9 * COUT];
    const int tid = threadIdx.x;
    const int px = tid & 31, oct = tid >> 5;
    const int w0 = blockIdx.x * 32, h0 = blockIdx.y * 8, b = blockIdx.z;
    const int ocb = oct * OCPT;

    unsigned long long acc[8][OCPT / 2];
#pragma unroll
    for (int j = 0; j < OCPT / 2; j++) {
        unsigned long long bp = pk2(bias[ocb + 2 * j], bias[ocb + 2 * j + 1]);
#pragma unroll
        for (int r = 0; r < 8; r++) acc[r][j] = bp;
    }

    for (int c0 = 0; c0 < CINP; c0 += 4) {
        __syncthreads();
        // input halo for 4 channels: 10 rows x 34 cols each
        for (int idx = tid; idx < 4 * 10 * 34; idx += 256) {
            int c = idx / 340, r2 = idx % 340, rr = r2 / 34, cc = r2 % 34;
            int gh = h0 + rr - 1, gw = w0 + cc - 1;
            int ci = c0 + c;
            float v = 0.f;
            if (gh >= 0 && gh < H_ && gw >= 0 && gw < W_) {
                if (SPLIT) {
                    if (ci < 128)      v = in [((b * 128 + ci)        * H_ + gh) * W_ + gw];
                    else if (ci < 209) v = in2[((b * 81 + (ci - 128)) * H_ + gh) * W_ + gw];
                } else {
                    v = in[((b * CIN + ci) * H_ + gh) * W_ + gw];
                }
            }
            in_s[c][rr][cc] = v;
        }
        // weights chunk [4][9][COUT] is contiguous in wr
        for (int idx = tid; idx < 4 * 9 * COUT; idx += 256)
            w_s[idx] = wr[c0 * 9 * COUT + idx];
        __syncthreads();

#pragma unroll
        for (int c = 0; c < 4; c++) {
#pragma unroll
            for (int ky = 0; ky < 3; ky++) {
#pragma unroll
                for (int kx = 0; kx < 3; kx++) {
                    const unsigned long long* wrow =
                        reinterpret_cast<const unsigned long long*>(
                            &w_s[((c * 9) + ky * 3 + kx) * COUT + ocb]);
                    unsigned long long wp[OCPT / 2];
#pragma unroll
                    for (int j = 0; j < OCPT / 2; j++) wp[j] = wrow[j];
#pragma unroll
                    for (int r = 0; r < 8; r++) {
                        float v = in_s[c][r + ky][px + kx];
                        unsigned long long vv = pk2(v, v);
#pragma unroll
                        for (int j = 0; j < OCPT / 2; j++) fma2(acc[r][j], vv, wp[j]);
                    }
                }
            }
        }
    }

#pragma unroll
    for (int r = 0; r < 8; r++) {
#pragma unroll
        for (int j = 0; j < OCPT / 2; j++) {
            float a, bv;
            upk2(acc[r][j], a, bv);
            if (LEAKY) { a = fmaxf(a, 0.1f * a); bv = fmaxf(bv, 0.1f * bv); }
            int oc = ocb + 2 * j;
            out[((b * COUT + oc    ) * H_ + h0 + r) * W_ + w0 + px] = a;
            out[((b * COUT + oc + 1) * H_ + h0 + r) * W_ + w0 + px] = bv;
        }
    }
}

// ---------------- conv4: 32 -> 2, no activation, tiny ----------------
__global__ void __launch_bounds__(256) k_conv4(const float* __restrict__ in,
                                               const float* __restrict__ w,
                                               const float* __restrict__ bias,
                                               float* __restrict__ out) {
    __shared__ __align__(16) float in_s[4][10][34];
    __shared__ float w_s[2 * 32 * 9];
    const int tid = threadIdx.x;
    const int col = tid & 31, row = tid >> 5;
    const int w0 = blockIdx.x * 32, h0 = blockIdx.y * 8, b = blockIdx.z;

    for (int idx = tid; idx < 576; idx += 256)
        w_s[idx] = w[idx];          // raw [oc][ci][k]
    __syncthreads();

    float acc0 = bias[0], acc1 = bias[1];
    for (int c0 = 0; c0 < 32; c0 += 4) {
        __syncthreads();
        for (int idx = tid; idx < 4 * 10 * 34; idx += 256) {
            int c = idx / 340, r2 = idx % 340, rr = r2 / 34, cc = r2 % 34;
            int gh = h0 + rr - 1, gw = w0 + cc - 1;
            float v = 0.f;
            if (gh >= 0 && gh < H_ && gw >= 0 && gw < W_)
                v = in[((b * 32 + c0 + c) * H_ + gh) * W_ + gw];
            in_s[c][rr][cc] = v;
        }
        __syncthreads();
#pragma unroll
        for (int c = 0; c < 4; c++)
#pragma unroll
            for (int ky = 0; ky < 3; ky++)
#pragma unroll
                for (int kx = 0; kx < 3; kx++) {
                    float v = in_s[c][row + ky][col + kx];
                    int ci = c0 + c, k = ky * 3 + kx;
                    acc0 += v * w_s[      ci * 9 + k];
                    acc1 += v * w_s[288 + ci * 9 + k];
                }
    }
    out[((b * 2 + 0) * H_ + h0 + row) * W_ + w0 + col] = acc0;
    out[((b * 2 + 1) * H_ + h0 + row) * W_ + w0 + col] = acc1;
}

// ---------------- launch ----------------
extern "C" void kernel_launch(void* const* d_in, const int* in_sizes, int n_in,
                              void* d_out, int out_size) {
    (void)in_sizes; (void)n_in; (void)out_size;
    const float* x1 = (const float*)d_in[0];
    const float* x2 = (const float*)d_in[1];
    const float* w1 = (const float*)d_in[2];
    const float* b1 = (const float*)d_in[3];
    const float* w2 = (const float*)d_in[4];
    const float* b2 = (const float*)d_in[5];
    const float* w3 = (const float*)d_in[6];
    const float* b3 = (const float*)d_in[7];
    const float* w4 = (const float*)d_in[8];
    const float* b4 = (const float*)d_in[9];
    float* out = (float*)d_out;

    float *corr, *h1, *h2, *h3, *w1r, *w2r, *w3r;
    cudaGetSymbolAddress((void**)&corr, g_corr);
    cudaGetSymbolAddress((void**)&h1,   g_h1);
    cudaGetSymbolAddress((void**)&h2,   g_h2);
    cudaGetSymbolAddress((void**)&h3,   g_h3);
    cudaGetSymbolAddress((void**)&w1r,  g_w1r);
    cudaGetSymbolAddress((void**)&w2r,  g_w2r);
    cudaGetSymbolAddress((void**)&w3r,  g_w3r);

    k_reorder<<<(212 * 9 * 64 + 255) / 256, 256>>>(w1, w1r, 209, 212, 64);
    k_reorder<<<(64  * 9 * 64 + 255) / 256, 256>>>(w2, w2r, 64, 64, 64);
    k_reorder<<<(64  * 9 * 32 + 255) / 256, 256>>>(w3, w3r, 64, 64, 32);

    dim3 grid(W_ / 32, H_ / 8, B_);   // (7, 16, 8)
    k_corr<<<grid, 256>>>(x1, x2);
    k_conv<209, 212, 64, 8, true,  true ><<<grid, 256>>>(x1, corr, w1r, b1, h1);
    k_conv< 64,  64, 64, 8, true,  false><<<grid, 256>>>(h1, nullptr, w2r, b2, h2);
    k_conv< 64,  64, 32, 4, true,  false><<<grid, 256>>>(h2, nullptr, w3r, b3, h3);
    k_conv4<<<grid, 256>>>(h3, w4, b4, out);
}